// round 7
// baseline (speedup 1.0000x reference)
#include <cuda_runtime.h>

#define NN       50000
#define DIM      512
#define KMAX     32
#define NTHREADS 128
#define SENT     0x7FC00DADu   // NaN payload sentinel: unreachable by finite math

// Score chain: packed word per node  [63:32]=float eknew bits, [31:0]=ready flag.
__device__ unsigned long long g_score[NN];
__device__ float g_eq[NN];    // feats[i].wq_w + wq_b
__device__ float g_ek0[NN];   // feats[i].wk_w + wk_b

__device__ __forceinline__ unsigned long long ld_relaxed_u64(const unsigned long long* p) {
    unsigned long long v;
    asm volatile("ld.global.relaxed.gpu.b64 %0, [%1];" : "=l"(v) : "l"(p) : "memory");
    return v;
}
__device__ __forceinline__ void st_relaxed_u64(unsigned long long* p, unsigned long long v) {
    asm volatile("st.global.relaxed.gpu.b64 [%0], %1;" :: "l"(p), "l"(v) : "memory");
}
__device__ __forceinline__ float ld_relaxed_f32(const float* p) {
    float v;
    asm volatile("ld.global.relaxed.gpu.f32 %0, [%1];" : "=f"(v) : "l"(p) : "memory");
    return v;
}
__device__ __forceinline__ void st_relaxed_f32(float* p, float v) {
    asm volatile("st.global.relaxed.gpu.f32 [%0], %1;" :: "l"(p), "f"(v) : "memory");
}

// One warp per row: eq/ek0 GEMV; reset score flags; sentinel-fill out.
__global__ void pre_kernel(const float* __restrict__ feats,
                           const float* __restrict__ wq_w,
                           const float* __restrict__ wq_b,
                           const float* __restrict__ wk_w,
                           const float* __restrict__ wk_b,
                           float*       out)
{
    int gtid = blockIdx.x * blockDim.x + threadIdx.x;
    if (gtid < NN) g_score[gtid] = 0ull;

    // Sentinel-fill out: NN*DIM floats = 6.4M float4, 1.5625M threads -> ~4.1 each
    {
        const unsigned s = SENT;
        float4 sv = make_float4(__uint_as_float(s), __uint_as_float(s),
                                __uint_as_float(s), __uint_as_float(s));
        float4* o4 = (float4*)out;
        const int total4 = NN * DIM / 4;
        const int nthr   = (NN * 32 + 255) / 256 * 256;
        for (int j = gtid; j < total4; j += nthr) o4[j] = sv;
    }

    int row_i = gtid >> 5;
    int lane  = gtid & 31;
    if (row_i >= NN) return;

    const float4* row = (const float4*)(feats + (size_t)row_i * DIM);
    const float4* q4  = (const float4*)wq_w;
    const float4* k4  = (const float4*)wk_w;
    float sq = 0.f, sk = 0.f;
    #pragma unroll
    for (int j = lane; j < DIM / 4; j += 32) {
        float4 f = row[j];
        float4 q = q4[j];
        float4 k = k4[j];
        sq += f.x*q.x + f.y*q.y + f.z*q.z + f.w*q.w;
        sk += f.x*k.x + f.y*k.y + f.z*k.z + f.w*k.w;
    }
    #pragma unroll
    for (int o = 16; o > 0; o >>= 1) {
        sq += __shfl_down_sync(0xffffffffu, sq, o);
        sk += __shfl_down_sync(0xffffffffu, sk, o);
    }
    if (lane == 0) {
        g_eq[row_i]  = sq + *wq_b;
        g_ek0[row_i] = sk + *wk_b;
    }
}

__global__ void __launch_bounds__(NTHREADS, 10)
attn_kernel(const float* __restrict__ feats,
            const int*   __restrict__ neighbors,
            const int*   __restrict__ deg,
            const float* __restrict__ wk_b,
            float*       out)
{
    __shared__ float        s_aL[KMAX], s_aE[KMAX];
    __shared__ const float* s_pL[KMAX];
    __shared__ const float* s_pE[KMAX];
    __shared__ int          s_cnt;

    const int i   = blockIdx.x;
    const int tid = threadIdx.x;
    const int d   = deg[i];

    // ---- prefetch center row early (independent of all waits) ----
    const float* fi = feats + (size_t)i * DIM;
    float acc0 = fi[tid];
    float acc1 = fi[tid + 128];
    float acc2 = fi[tid + 256];
    float acc3 = fi[tid + 384];

    if (tid < 32) {
        const bool valid = tid < d;
        int   nb    = 0;
        bool  early = false;
        float ej    = 0.f;
        if (valid) {
            nb    = neighbors[i * KMAX + tid];
            early = nb < i;
            if (early) {
                unsigned long long w;
                int it = 0;
                while ((unsigned)((w = ld_relaxed_u64(&g_score[nb]))) == 0u) {
                    if (++it > 8) __nanosleep(20);
                }
                ej = __uint_as_float((unsigned)(w >> 32));
            } else {
                ej = __ldg(&g_ek0[nb]);
            }
        }

        // ---- softmax over valid scores ----
        const float wkb = *wk_b;
        const float ei  = g_eq[i];
        float e = valid ? ei * ej : -3.4e38f;
        float m = e;
        #pragma unroll
        for (int o = 16; o > 0; o >>= 1)
            m = fmaxf(m, __shfl_xor_sync(0xffffffffu, m, o));
        float ex  = valid ? expf(e - m) : 0.f;
        float s   = ex;
        float num = ex * (ej - wkb);
        #pragma unroll
        for (int o = 16; o > 0; o >>= 1) {
            s   += __shfl_xor_sync(0xffffffffu, s, o);
            num += __shfl_xor_sync(0xffffffffu, num, o);
        }

        // ---- publish score IMMEDIATELY ----
        if (tid == 0) {
            float ekn = g_ek0[i] + ((d > 0) ? num / s : 0.f);
            unsigned long long w =
                ((unsigned long long)__float_as_uint(ekn) << 32) | 1ull;
            st_relaxed_u64(&g_score[i], w);
        }

        // ---- compact neighbors into late / early lists ----
        unsigned vm = __ballot_sync(0xffffffffu, valid);
        unsigned em = __ballot_sync(0xffffffffu, valid && early);
        unsigned lm = vm & ~em;
        if (valid) {
            float a = ex / s;
            const float* p = (early ? out : feats) + (size_t)nb * DIM;
            unsigned below = (1u << tid) - 1u;
            if (early) { int k = __popc(em & below); s_aE[k] = a; s_pE[k] = p; }
            else       { int k = __popc(lm & below); s_aL[k] = a; s_pL[k] = p; }
        }
        if (tid == 0) s_cnt = __popc(lm) | (__popc(em) << 16);
    }
    __syncthreads();

    const int nL = s_cnt & 0xffff;
    const int nE = s_cnt >> 16;

    // ---- late rows: plain loads from feats, full MLP ----
    #pragma unroll 4
    for (int k = 0; k < nL; k++) {
        const float  a = s_aL[k];
        const float* r = s_pL[k];
        acc0 = fmaf(a, __ldg(r + tid),       acc0);
        acc1 = fmaf(a, __ldg(r + tid + 128), acc1);
        acc2 = fmaf(a, __ldg(r + tid + 256), acc2);
        acc3 = fmaf(a, __ldg(r + tid + 384), acc3);
    }

    // ---- early rows: sentinel-polled reads of out (data IS the flag) ----
    if (nE > 0) {
        float e0 = 0.f, e1 = 0.f, e2 = 0.f, e3 = 0.f;
        // fast path: assume ready, full MLP; sentinel (NaN) propagates
        #pragma unroll 4
        for (int k = 0; k < nE; k++) {
            const float  a = s_aE[k];
            const float* r = s_pE[k];
            e0 = fmaf(a, ld_relaxed_f32(r + tid),       e0);
            e1 = fmaf(a, ld_relaxed_f32(r + tid + 128), e1);
            e2 = fmaf(a, ld_relaxed_f32(r + tid + 256), e2);
            e3 = fmaf(a, ld_relaxed_f32(r + tid + 384), e3);
        }
        if (isnan(e0 + e1 + e2 + e3)) {
            // slow path: at least one row not ready yet -> per-word polling
            e0 = e1 = e2 = e3 = 0.f;
            for (int k = 0; k < nE; k++) {
                const float  a = s_aE[k];
                const float* r = s_pE[k];
                float v0 = ld_relaxed_f32(r + tid);
                float v1 = ld_relaxed_f32(r + tid + 128);
                float v2 = ld_relaxed_f32(r + tid + 256);
                float v3 = ld_relaxed_f32(r + tid + 384);
                while (__float_as_uint(v0) == SENT) { __nanosleep(20); v0 = ld_relaxed_f32(r + tid);       }
                while (__float_as_uint(v1) == SENT) { __nanosleep(20); v1 = ld_relaxed_f32(r + tid + 128); }
                while (__float_as_uint(v2) == SENT) { __nanosleep(20); v2 = ld_relaxed_f32(r + tid + 256); }
                while (__float_as_uint(v3) == SENT) { __nanosleep(20); v3 = ld_relaxed_f32(r + tid + 384); }
                e0 = fmaf(a, v0, e0);
                e1 = fmaf(a, v1, e1);
                e2 = fmaf(a, v2, e2);
                e3 = fmaf(a, v3, e3);
            }
        }
        acc0 += e0; acc1 += e1; acc2 += e2; acc3 += e3;
    }

    // ---- publish row: plain relaxed stores, no flag, no fence ----
    float* oi = out + (size_t)i * DIM;
    st_relaxed_f32(oi + tid,       acc0);
    st_relaxed_f32(oi + tid + 128, acc1);
    st_relaxed_f32(oi + tid + 256, acc2);
    st_relaxed_f32(oi + tid + 384, acc3);
}

extern "C" void kernel_launch(void* const* d_in, const int* in_sizes, int n_in,
                              void* d_out, int out_size) {
    const float* feats     = (const float*)d_in[0];
    const float* wq_w      = (const float*)d_in[1];
    const float* wq_b      = (const float*)d_in[2];
    const float* wk_w      = (const float*)d_in[3];
    const float* wk_b      = (const float*)d_in[4];
    const int*   neighbors = (const int*)d_in[5];
    const int*   deg       = (const int*)d_in[6];
    float*       out       = (float*)d_out;

    pre_kernel<<<(NN * 32 + 255) / 256, 256>>>(feats, wq_w, wq_b, wk_w, wk_b, out);
    attn_kernel<<<NN, NTHREADS>>>(feats, neighbors, deg, wk_b, out);
}